// round 16
// baseline (speedup 1.0000x reference)
#include <cuda_runtime.h>
#include <cuda_fp16.h>
#include <cstdint>

// ---------------------------------------------------------------------------
// out[M,N] = segment_mean(gather(cf, member_idx), segment_ids) @ W + b
// R16 = exact R12 (best: 105.0us) + ONE isolated change: mean kernel uses 8
// independent accumulator chains with plain scalar __ldg index loads (no
// alignment head loop, no int4, no store-policy changes -- R15's regression
// came from the serialized head loop bundled with other changes).
// GEMM: fp16 mma.sync, BK=64, 3-stage cp.async, frag double-buffer (HMMA
// ceiling). Sequential structure (overlap family closed: shared LTS cap).
// ---------------------------------------------------------------------------

#define MAX_ROWS_PAD 65664          // multiple of 128, >= padded M
#define AK 256

// Zero-initialized scratch. Rows >= M never written -> stay zero (no guards).
__device__ __half g_a[(size_t)MAX_ROWS_PAD * AK];
__device__ __half g_b[1024 * 512];          // [N][K] (W transposed)
__device__ int g_starts[65600];

// ---------------------------------------------------------------------------
// PTX helpers (baseline sm_80 features — safe through compute_103 PTX)
// ---------------------------------------------------------------------------
__device__ __forceinline__ uint32_t smem_u32(const void* p) {
    uint32_t a;
    asm("{ .reg .u64 t; cvta.to.shared.u64 t, %1; cvt.u32.u64 %0, t; }"
        : "=r"(a) : "l"(p));
    return a;
}

#define CP16(dst, src) \
    asm volatile("cp.async.cg.shared.global [%0], [%1], 16;" \
                 :: "r"(dst), "l"(src) : "memory")
#define CP_COMMIT() asm volatile("cp.async.commit_group;" ::: "memory")
#define CP_WAIT1()  asm volatile("cp.async.wait_group 1;" ::: "memory")

#define LDM4(r, a) \
    asm volatile("ldmatrix.sync.aligned.m8n8.x4.shared.b16 {%0,%1,%2,%3}, [%4];" \
                 : "=r"((r)[0]), "=r"((r)[1]), "=r"((r)[2]), "=r"((r)[3]) \
                 : "r"(a))

#define MMA_F16(d, a, b0, b1) \
    asm volatile("mma.sync.aligned.m16n8k16.row.col.f32.f16.f16.f32 " \
                 "{%0,%1,%2,%3}, {%4,%5,%6,%7}, {%8,%9}, {%0,%1,%2,%3};" \
                 : "+f"((d)[0]), "+f"((d)[1]), "+f"((d)[2]), "+f"((d)[3]) \
                 : "r"((a)[0]), "r"((a)[1]), "r"((a)[2]), "r"((a)[3]), \
                   "r"(b0), "r"(b1))

#define ACC4(a, v) { (a).x += (v).x; (a).y += (v).y; (a).z += (v).z; (a).w += (v).w; }

// ---------------------------------------------------------------------------
// Kernel 0: prep = segment starts (blocks [0, nbs)) + W prepack (rest).
// ---------------------------------------------------------------------------
__global__ void prep_kernel(const int* __restrict__ seg, int num_members, int num_cells,
                            const float* __restrict__ W, int K, int N, int nbs) {
    const int bid = blockIdx.x;
    if (bid < nbs) {
        int i = bid * 256 + threadIdx.x;
        if (i > num_members) return;
        int cur  = (i < num_members) ? __ldg(&seg[i]) : num_cells;
        int prev = (i > 0) ? __ldg(&seg[i - 1]) : -1;
        for (int c = prev + 1; c <= cur; c++) g_starts[c] = i;
        return;
    }
    __shared__ float t[32][33];
    const int b2 = bid - nbs;
    const int ktiles = K >> 5;
    const int kb = (b2 % ktiles) * 32, nb = (b2 / ktiles) * 32;
    const int tx = threadIdx.x & 31, ty = threadIdx.x >> 5;   // 32 x 8
#pragma unroll
    for (int i = 0; i < 4; i++)
        t[ty + i * 8][tx] = W[(size_t)(kb + ty + i * 8) * N + nb + tx];
    __syncthreads();
#pragma unroll
    for (int i = 0; i < 4; i++)
        g_b[(size_t)(nb + ty + i * 8) * K + kb + tx] =
            __float2half_rn(t[tx][ty + i * 8]);
}

// ---------------------------------------------------------------------------
// Kernel 1: segment mean -> fp16. 128 threads = 2 cells per block (64 each).
// 8 independent accumulator chains; scalar __ldg index loads (independent).
// ---------------------------------------------------------------------------
__global__ void mean_kernel(const float4* __restrict__ cf4,
                            const int* __restrict__ midx,
                            int K4, int M) {
    const int c = blockIdx.x * 2 + (threadIdx.x >> 6);
    if (c >= M) return;
    const int tid = threadIdx.x & 63;
    const int start = __ldg(&g_starts[c]);
    const int end   = __ldg(&g_starts[c + 1]);

    float4 a0 = make_float4(0.f, 0.f, 0.f, 0.f);
    float4 a1 = a0, a2 = a0, a3 = a0;
    float4 a4 = a0, a5 = a0, a6 = a0, a7 = a0;

    int j = start;
    for (; j + 8 <= end; j += 8) {
        int i0 = __ldg(&midx[j])     * K4;
        int i1 = __ldg(&midx[j + 1]) * K4;
        int i2 = __ldg(&midx[j + 2]) * K4;
        int i3 = __ldg(&midx[j + 3]) * K4;
        int i4 = __ldg(&midx[j + 4]) * K4;
        int i5 = __ldg(&midx[j + 5]) * K4;
        int i6 = __ldg(&midx[j + 6]) * K4;
        int i7 = __ldg(&midx[j + 7]) * K4;
        float4 v0 = cf4[(size_t)i0 + tid];
        float4 v1 = cf4[(size_t)i1 + tid];
        float4 v2 = cf4[(size_t)i2 + tid];
        float4 v3 = cf4[(size_t)i3 + tid];
        float4 v4 = cf4[(size_t)i4 + tid];
        float4 v5 = cf4[(size_t)i5 + tid];
        float4 v6 = cf4[(size_t)i6 + tid];
        float4 v7 = cf4[(size_t)i7 + tid];
        ACC4(a0, v0); ACC4(a1, v1); ACC4(a2, v2); ACC4(a3, v3);
        ACC4(a4, v4); ACC4(a5, v5); ACC4(a6, v6); ACC4(a7, v7);
    }
    for (; j + 4 <= end; j += 4) {
        int i0 = __ldg(&midx[j])     * K4;
        int i1 = __ldg(&midx[j + 1]) * K4;
        int i2 = __ldg(&midx[j + 2]) * K4;
        int i3 = __ldg(&midx[j + 3]) * K4;
        float4 v0 = cf4[(size_t)i0 + tid];
        float4 v1 = cf4[(size_t)i1 + tid];
        float4 v2 = cf4[(size_t)i2 + tid];
        float4 v3 = cf4[(size_t)i3 + tid];
        ACC4(a0, v0); ACC4(a1, v1); ACC4(a2, v2); ACC4(a3, v3);
    }
    for (; j < end; j++) {
        int i0 = __ldg(&midx[j]) * K4;
        float4 v0 = cf4[(size_t)i0 + tid];
        ACC4(a0, v0);
    }

    float inv = 1.0f / fmaxf((float)(end - start), 1.0f);
    float sx = ((a0.x + a1.x) + (a2.x + a3.x)) + ((a4.x + a5.x) + (a6.x + a7.x));
    float sy = ((a0.y + a1.y) + (a2.y + a3.y)) + ((a4.y + a5.y) + (a6.y + a7.y));
    float sz = ((a0.z + a1.z) + (a2.z + a3.z)) + ((a4.z + a5.z) + (a6.z + a7.z));
    float sw = ((a0.w + a1.w) + (a2.w + a3.w)) + ((a4.w + a5.w) + (a6.w + a7.w));
    __half2 h0 = __floats2half2_rn(sx * inv, sy * inv);
    __half2 h1 = __floats2half2_rn(sz * inv, sw * inv);
    uint2 pk;
    pk.x = *(uint32_t*)&h0;
    pk.y = *(uint32_t*)&h1;
    ((uint2*)g_a)[(size_t)c * K4 + tid] = pk;
}

// ---------------------------------------------------------------------------
// Kernel 2: fp16 mma.sync GEMM with fragment double-buffering (R12 body,
// byte-identical). CTA 128x128, BK=64, 8 warps (4M x 2N), warp tile 32x64.
// Smem rows 128B, swizzle ch^=(row&7). 3 stages x 32KB cp.async pipeline.
// ---------------------------------------------------------------------------
#define STAGE_BYTES 32768u
#define SEC_BYTES   16384u
#define NSTAGE      3

__global__ __launch_bounds__(256, 2)
void gemm_mma_kernel(const float* __restrict__ bias, float* __restrict__ C,
                     int M, int N, int K) {
    extern __shared__ char smem[];
    const uint32_t sb = smem_u32(smem);
    const int tid  = threadIdx.x;
    const int wid  = tid >> 5, lane = tid & 31;
    const int wm   = wid & 3;
    const int wn   = wid >> 2;
    const int bm   = blockIdx.x * 128, bn = blockIdx.y * 128;
    const size_t rowb = (size_t)K * 2;

    const char* pA = (const char*)g_a + (size_t)bm * rowb;
    const char* pB = (const char*)g_b + (size_t)bn * rowb;

    uint32_t sdst[4];
    int lrow[4], lch[4];
#pragma unroll
    for (int i = 0; i < 4; i++) {
        int idx = i * 256 + tid;
        lrow[i] = idx >> 3;
        lch[i]  = idx & 7;
        sdst[i] = (uint32_t)(lrow[i] * 128 + ((lch[i] ^ (lrow[i] & 7)) << 4));
    }

    float acc[2][8][4];
#pragma unroll
    for (int g = 0; g < 2; g++)
#pragma unroll
        for (int n = 0; n < 8; n++)
#pragma unroll
            for (int j = 0; j < 4; j++) acc[g][n][j] = 0.f;

    const int a_r = (lane & 15);
    const int a_cadd = (lane >> 4);
    const int b_r = (lane & 7) + ((lane >> 4) << 3);
    const int b_cadd = ((lane >> 3) & 1);

    const int nit = K >> 6;

#pragma unroll
    for (int pre = 0; pre < 2; pre++) {
        const uint32_t sbase = sb + (uint32_t)pre * STAGE_BYTES;
        const size_t kt = (size_t)pre * 128;
#pragma unroll
        for (int i = 0; i < 4; i++) {
            CP16(sbase + sdst[i],             pA + (size_t)lrow[i] * rowb + kt + lch[i] * 16);
            CP16(sbase + SEC_BYTES + sdst[i], pB + (size_t)lrow[i] * rowb + kt + lch[i] * 16);
        }
        CP_COMMIT();
    }

    uint32_t af[2][2][4];
    uint32_t bf[2][4][4];

    for (int it = 0; it < nit; it++) {
        const uint32_t stg = sb + (uint32_t)(it % NSTAGE) * STAGE_BYTES;
        CP_WAIT1();
        __syncthreads();

        if (it + 2 < nit) {
            const uint32_t sbase = sb + (uint32_t)((it + 2) % NSTAGE) * STAGE_BYTES;
            const size_t kt = (size_t)(it + 2) * 128;
#pragma unroll
            for (int i = 0; i < 4; i++) {
                CP16(sbase + sdst[i],             pA + (size_t)lrow[i] * rowb + kt + lch[i] * 16);
                CP16(sbase + SEC_BYTES + sdst[i], pB + (size_t)lrow[i] * rowb + kt + lch[i] * 16);
            }
            CP_COMMIT();
        } else {
            CP_COMMIT();
        }

#pragma unroll
        for (int g = 0; g < 2; g++) {
            int row = wm * 32 + g * 16 + a_r;
            int ch  = a_cadd;
            LDM4(af[0][g], stg + row * 128 + ((ch ^ (row & 7)) << 4));
        }
#pragma unroll
        for (int h = 0; h < 4; h++) {
            int row = wn * 64 + h * 16 + b_r;
            int ch  = b_cadd;
            LDM4(bf[0][h], stg + SEC_BYTES + row * 128 + ((ch ^ (row & 7)) << 4));
        }

#pragma unroll
        for (int s = 0; s < 4; s++) {
            const int cur = s & 1, nxt = cur ^ 1;
            if (s < 3) {
#pragma unroll
                for (int g = 0; g < 2; g++) {
                    int row = wm * 32 + g * 16 + a_r;
                    int ch  = (s + 1) * 2 + a_cadd;
                    LDM4(af[nxt][g], stg + row * 128 + ((ch ^ (row & 7)) << 4));
                }
#pragma unroll
                for (int h = 0; h < 4; h++) {
                    int row = wn * 64 + h * 16 + b_r;
                    int ch  = (s + 1) * 2 + b_cadd;
                    LDM4(bf[nxt][h], stg + SEC_BYTES + row * 128 + ((ch ^ (row & 7)) << 4));
                }
            }
#pragma unroll
            for (int h = 0; h < 4; h++)
#pragma unroll
                for (int g = 0; g < 2; g++) {
                    MMA_F16(acc[g][h * 2],     af[cur][g], bf[cur][h][0], bf[cur][h][1]);
                    MMA_F16(acc[g][h * 2 + 1], af[cur][g], bf[cur][h][2], bf[cur][h][3]);
                }
        }
    }

#pragma unroll
    for (int g = 0; g < 2; g++) {
        int row0 = bm + wm * 32 + g * 16 + (lane >> 2);
        int row1 = row0 + 8;
#pragma unroll
        for (int n = 0; n < 8; n++) {
            int col = bn + wn * 64 + n * 8 + (lane & 3) * 2;
            float2 bb = *(const float2*)&bias[col];
            if (row0 < M) {
                float2 o = make_float2(acc[g][n][0] + bb.x, acc[g][n][1] + bb.y);
                *(float2*)&C[(size_t)row0 * N + col] = o;
            }
            if (row1 < M) {
                float2 o = make_float2(acc[g][n][2] + bb.x, acc[g][n][3] + bb.y);
                *(float2*)&C[(size_t)row1 * N + col] = o;
            }
        }
    }
}

// ---------------------------------------------------------------------------
// Launch (sequential: prep -> mean -> gemm)
// ---------------------------------------------------------------------------
extern "C" void kernel_launch(void* const* d_in, const int* in_sizes, int n_in,
                              void* d_out, int out_size) {
    const float* cf   = (const float*)d_in[0];
    const int* midx   = (const int*)d_in[1];
    const int* seg    = (const int*)d_in[2];
    const float* W    = (const float*)d_in[4];
    const float* bias = (const float*)d_in[5];
    float* out = (float*)d_out;

    const int N = in_sizes[5];           // 512
    const int K = in_sizes[4] / N;       // 256
    const int M = out_size / N;          // 50000
    const int num_members = in_sizes[1]; // 400000
    const int K4 = K / 4;

    cudaFuncSetAttribute(gemm_mma_kernel,
                         cudaFuncAttributeMaxDynamicSharedMemorySize,
                         (int)(NSTAGE * STAGE_BYTES));

    const int nbs = (num_members + 256) / 256;            // starts blocks
    const int nbw = (K / 32) * (N / 32);                  // prepw tiles
    prep_kernel<<<nbs + nbw, 256>>>(seg, num_members, M, W, K, N, nbs);

    mean_kernel<<<(M + 1) / 2, 128>>>((const float4*)cf, midx, K4, M);

    dim3 grid((M + 127) / 128, N / 128);
    gemm_mma_kernel<<<grid, 256, NSTAGE * STAGE_BYTES>>>(bias, out, M, N, K);
}

// round 17
// speedup vs baseline: 1.1973x; 1.1973x over previous
#include <cuda_runtime.h>
#include <cuda_fp16.h>
#include <cstdint>

// ---------------------------------------------------------------------------
// out[M,N] = segment_mean(gather(cf, member_idx), segment_ids) @ W + b
// R17 = exact R12 revert (verified best: 105.0us).
// Pipeline: prep (starts[] + W transpose->fp16, one kernel) -> mean (unroll-4,
// the measured L1tex-queue sweet spot per the B300 spread model; unroll-8
// regressed +16-20us twice) -> fp16 mma.sync GEMM (BK=64, 3-stage cp.async,
// register-fragment double-buffering, 2 CTAs/SM -- at the legacy-HMMA issue
// ceiling ~267 TF/s; tcgen05 is unreachable through the compute_103 PTX
// toolchain). Sequential structure: 5 overlap variants all regressed because
// mean and GEMM share the LTS bandwidth cap.
// rel_err ~2.9e-4 (fp16 single-term, 3.4x under the 1e-3 threshold).
// ---------------------------------------------------------------------------

#define MAX_ROWS_PAD 65664          // multiple of 128, >= padded M
#define AK 256

// Zero-initialized scratch. Rows >= M never written -> stay zero (no guards).
__device__ __half g_a[(size_t)MAX_ROWS_PAD * AK];
__device__ __half g_b[1024 * 512];          // [N][K] (W transposed)
__device__ int g_starts[65600];

// ---------------------------------------------------------------------------
// PTX helpers (baseline sm_80 features — safe through compute_103 PTX)
// ---------------------------------------------------------------------------
__device__ __forceinline__ uint32_t smem_u32(const void* p) {
    uint32_t a;
    asm("{ .reg .u64 t; cvta.to.shared.u64 t, %1; cvt.u32.u64 %0, t; }"
        : "=r"(a) : "l"(p));
    return a;
}

#define CP16(dst, src) \
    asm volatile("cp.async.cg.shared.global [%0], [%1], 16;" \
                 :: "r"(dst), "l"(src) : "memory")
#define CP_COMMIT() asm volatile("cp.async.commit_group;" ::: "memory")
#define CP_WAIT1()  asm volatile("cp.async.wait_group 1;" ::: "memory")

#define LDM4(r, a) \
    asm volatile("ldmatrix.sync.aligned.m8n8.x4.shared.b16 {%0,%1,%2,%3}, [%4];" \
                 : "=r"((r)[0]), "=r"((r)[1]), "=r"((r)[2]), "=r"((r)[3]) \
                 : "r"(a))

#define MMA_F16(d, a, b0, b1) \
    asm volatile("mma.sync.aligned.m16n8k16.row.col.f32.f16.f16.f32 " \
                 "{%0,%1,%2,%3}, {%4,%5,%6,%7}, {%8,%9}, {%0,%1,%2,%3};" \
                 : "+f"((d)[0]), "+f"((d)[1]), "+f"((d)[2]), "+f"((d)[3]) \
                 : "r"((a)[0]), "r"((a)[1]), "r"((a)[2]), "r"((a)[3]), \
                   "r"(b0), "r"(b1))

#define ACC4(a, v) { (a).x += (v).x; (a).y += (v).y; (a).z += (v).z; (a).w += (v).w; }

// ---------------------------------------------------------------------------
// Kernel 0: prep = segment starts (blocks [0, nbs)) + W prepack (rest).
// ---------------------------------------------------------------------------
__global__ void prep_kernel(const int* __restrict__ seg, int num_members, int num_cells,
                            const float* __restrict__ W, int K, int N, int nbs) {
    const int bid = blockIdx.x;
    if (bid < nbs) {
        int i = bid * 256 + threadIdx.x;
        if (i > num_members) return;
        int cur  = (i < num_members) ? __ldg(&seg[i]) : num_cells;
        int prev = (i > 0) ? __ldg(&seg[i - 1]) : -1;
        for (int c = prev + 1; c <= cur; c++) g_starts[c] = i;
        return;
    }
    __shared__ float t[32][33];
    const int b2 = bid - nbs;
    const int ktiles = K >> 5;
    const int kb = (b2 % ktiles) * 32, nb = (b2 / ktiles) * 32;
    const int tx = threadIdx.x & 31, ty = threadIdx.x >> 5;   // 32 x 8
#pragma unroll
    for (int i = 0; i < 4; i++)
        t[ty + i * 8][tx] = W[(size_t)(kb + ty + i * 8) * N + nb + tx];
    __syncthreads();
#pragma unroll
    for (int i = 0; i < 4; i++)
        g_b[(size_t)(nb + ty + i * 8) * K + kb + tx] =
            __float2half_rn(t[tx][ty + i * 8]);
}

// ---------------------------------------------------------------------------
// Kernel 1: segment mean -> fp16. 128 threads = 2 cells per block (64 each).
// Unroll-4 independent accumulator chains (measured L1tex-queue sweet spot).
// ---------------------------------------------------------------------------
__global__ void mean_kernel(const float4* __restrict__ cf4,
                            const int* __restrict__ midx,
                            int K4, int M) {
    const int c = blockIdx.x * 2 + (threadIdx.x >> 6);
    if (c >= M) return;
    const int tid = threadIdx.x & 63;
    const int start = __ldg(&g_starts[c]);
    const int end   = __ldg(&g_starts[c + 1]);

    float4 a0 = make_float4(0.f, 0.f, 0.f, 0.f);
    float4 a1 = a0, a2 = a0, a3 = a0;

    int j = start;
    for (; j + 4 <= end; j += 4) {
        int i0 = __ldg(&midx[j])     * K4;
        int i1 = __ldg(&midx[j + 1]) * K4;
        int i2 = __ldg(&midx[j + 2]) * K4;
        int i3 = __ldg(&midx[j + 3]) * K4;
        float4 v0 = cf4[(size_t)i0 + tid];
        float4 v1 = cf4[(size_t)i1 + tid];
        float4 v2 = cf4[(size_t)i2 + tid];
        float4 v3 = cf4[(size_t)i3 + tid];
        ACC4(a0, v0); ACC4(a1, v1); ACC4(a2, v2); ACC4(a3, v3);
    }
    for (; j < end; j++) {
        int i0 = __ldg(&midx[j]) * K4;
        float4 v0 = cf4[(size_t)i0 + tid];
        ACC4(a0, v0);
    }

    float inv = 1.0f / fmaxf((float)(end - start), 1.0f);
    __half2 h0 = __floats2half2_rn((a0.x + a1.x + a2.x + a3.x) * inv,
                                   (a0.y + a1.y + a2.y + a3.y) * inv);
    __half2 h1 = __floats2half2_rn((a0.z + a1.z + a2.z + a3.z) * inv,
                                   (a0.w + a1.w + a2.w + a3.w) * inv);
    uint2 pk;
    pk.x = *(uint32_t*)&h0;
    pk.y = *(uint32_t*)&h1;
    ((uint2*)g_a)[(size_t)c * K4 + tid] = pk;
}

// ---------------------------------------------------------------------------
// Kernel 2: fp16 mma.sync GEMM with fragment double-buffering.
// CTA 128x128, BK=64, 8 warps (4M x 2N), warp tile 32x64.
// Smem rows 128B, swizzle ch^=(row&7). 3 stages x 32KB cp.async pipeline.
// ---------------------------------------------------------------------------
#define STAGE_BYTES 32768u
#define SEC_BYTES   16384u
#define NSTAGE      3

__global__ __launch_bounds__(256, 2)
void gemm_mma_kernel(const float* __restrict__ bias, float* __restrict__ C,
                     int M, int N, int K) {
    extern __shared__ char smem[];
    const uint32_t sb = smem_u32(smem);
    const int tid  = threadIdx.x;
    const int wid  = tid >> 5, lane = tid & 31;
    const int wm   = wid & 3;
    const int wn   = wid >> 2;
    const int bm   = blockIdx.x * 128, bn = blockIdx.y * 128;
    const size_t rowb = (size_t)K * 2;

    const char* pA = (const char*)g_a + (size_t)bm * rowb;
    const char* pB = (const char*)g_b + (size_t)bn * rowb;

    uint32_t sdst[4];
    int lrow[4], lch[4];
#pragma unroll
    for (int i = 0; i < 4; i++) {
        int idx = i * 256 + tid;
        lrow[i] = idx >> 3;
        lch[i]  = idx & 7;
        sdst[i] = (uint32_t)(lrow[i] * 128 + ((lch[i] ^ (lrow[i] & 7)) << 4));
    }

    float acc[2][8][4];
#pragma unroll
    for (int g = 0; g < 2; g++)
#pragma unroll
        for (int n = 0; n < 8; n++)
#pragma unroll
            for (int j = 0; j < 4; j++) acc[g][n][j] = 0.f;

    const int a_r = (lane & 15);
    const int a_cadd = (lane >> 4);
    const int b_r = (lane & 7) + ((lane >> 4) << 3);
    const int b_cadd = ((lane >> 3) & 1);

    const int nit = K >> 6;

#pragma unroll
    for (int pre = 0; pre < 2; pre++) {
        const uint32_t sbase = sb + (uint32_t)pre * STAGE_BYTES;
        const size_t kt = (size_t)pre * 128;
#pragma unroll
        for (int i = 0; i < 4; i++) {
            CP16(sbase + sdst[i],             pA + (size_t)lrow[i] * rowb + kt + lch[i] * 16);
            CP16(sbase + SEC_BYTES + sdst[i], pB + (size_t)lrow[i] * rowb + kt + lch[i] * 16);
        }
        CP_COMMIT();
    }

    uint32_t af[2][2][4];
    uint32_t bf[2][4][4];

    for (int it = 0; it < nit; it++) {
        const uint32_t stg = sb + (uint32_t)(it % NSTAGE) * STAGE_BYTES;
        CP_WAIT1();
        __syncthreads();

        if (it + 2 < nit) {
            const uint32_t sbase = sb + (uint32_t)((it + 2) % NSTAGE) * STAGE_BYTES;
            const size_t kt = (size_t)(it + 2) * 128;
#pragma unroll
            for (int i = 0; i < 4; i++) {
                CP16(sbase + sdst[i],             pA + (size_t)lrow[i] * rowb + kt + lch[i] * 16);
                CP16(sbase + SEC_BYTES + sdst[i], pB + (size_t)lrow[i] * rowb + kt + lch[i] * 16);
            }
            CP_COMMIT();
        } else {
            CP_COMMIT();
        }

#pragma unroll
        for (int g = 0; g < 2; g++) {
            int row = wm * 32 + g * 16 + a_r;
            int ch  = a_cadd;
            LDM4(af[0][g], stg + row * 128 + ((ch ^ (row & 7)) << 4));
        }
#pragma unroll
        for (int h = 0; h < 4; h++) {
            int row = wn * 64 + h * 16 + b_r;
            int ch  = b_cadd;
            LDM4(bf[0][h], stg + SEC_BYTES + row * 128 + ((ch ^ (row & 7)) << 4));
        }

#pragma unroll
        for (int s = 0; s < 4; s++) {
            const int cur = s & 1, nxt = cur ^ 1;
            if (s < 3) {
#pragma unroll
                for (int g = 0; g < 2; g++) {
                    int row = wm * 32 + g * 16 + a_r;
                    int ch  = (s + 1) * 2 + a_cadd;
                    LDM4(af[nxt][g], stg + row * 128 + ((ch ^ (row & 7)) << 4));
                }
#pragma unroll
                for (int h = 0; h < 4; h++) {
                    int row = wn * 64 + h * 16 + b_r;
                    int ch  = (s + 1) * 2 + b_cadd;
                    LDM4(bf[nxt][h], stg + SEC_BYTES + row * 128 + ((ch ^ (row & 7)) << 4));
                }
            }
#pragma unroll
            for (int h = 0; h < 4; h++)
#pragma unroll
                for (int g = 0; g < 2; g++) {
                    MMA_F16(acc[g][h * 2],     af[cur][g], bf[cur][h][0], bf[cur][h][1]);
                    MMA_F16(acc[g][h * 2 + 1], af[cur][g], bf[cur][h][2], bf[cur][h][3]);
                }
        }
    }

#pragma unroll
    for (int g = 0; g < 2; g++) {
        int row0 = bm + wm * 32 + g * 16 + (lane >> 2);
        int row1 = row0 + 8;
#pragma unroll
        for (int n = 0; n < 8; n++) {
            int col = bn + wn * 64 + n * 8 + (lane & 3) * 2;
            float2 bb = *(const float2*)&bias[col];
            if (row0 < M) {
                float2 o = make_float2(acc[g][n][0] + bb.x, acc[g][n][1] + bb.y);
                *(float2*)&C[(size_t)row0 * N + col] = o;
            }
            if (row1 < M) {
                float2 o = make_float2(acc[g][n][2] + bb.x, acc[g][n][3] + bb.y);
                *(float2*)&C[(size_t)row1 * N + col] = o;
            }
        }
    }
}

// ---------------------------------------------------------------------------
// Launch (sequential: prep -> mean -> gemm)
// ---------------------------------------------------------------------------
extern "C" void kernel_launch(void* const* d_in, const int* in_sizes, int n_in,
                              void* d_out, int out_size) {
    const float* cf   = (const float*)d_in[0];
    const int* midx   = (const int*)d_in[1];
    const int* seg    = (const int*)d_in[2];
    const float* W    = (const float*)d_in[4];
    const float* bias = (const float*)d_in[5];
    float* out = (float*)d_out;

    const int N = in_sizes[5];           // 512
    const int K = in_sizes[4] / N;       // 256
    const int M = out_size / N;          // 50000
    const int num_members = in_sizes[1]; // 400000
    const int K4 = K / 4;

    cudaFuncSetAttribute(gemm_mma_kernel,
                         cudaFuncAttributeMaxDynamicSharedMemorySize,
                         (int)(NSTAGE * STAGE_BYTES));

    const int nbs = (num_members + 256) / 256;            // starts blocks
    const int nbw = (K / 32) * (N / 32);                  // prepw tiles
    prep_kernel<<<nbs + nbw, 256>>>(seg, num_members, M, W, K, N, nbs);

    mean_kernel<<<(M + 1) / 2, 128>>>((const float4*)cf, midx, K4, M);

    dim3 grid((M + 127) / 128, N / 128);
    gemm_mma_kernel<<<grid, 256, NSTAGE * STAGE_BYTES>>>(bias, out, M, N, K);
}